// round 14
// baseline (speedup 1.0000x reference)
#include <cuda_runtime.h>
#include <cuda_bf16.h>
#include <cstdint>

#define SEQ   512
#define BAT   64
#define DH    1024
#define KP    3072                 // tri-split K' = 3*1024
#define MROWS (SEQ*BAT)            // 32768
#define BHD   (BAT*DH)             // 65536

#define GRID_REC 128
#define REC_THREADS 256
#define CH_A  768                  // phase-A k-chunk (4 splits)
#define CH_C  384                  // phase-C k-chunk (8 splits)
#define WPSZ  ((size_t)DH*KP)
#define LDT   72                   // smem row stride (bf16)
#define TSZ   (64*LDT)             // one 64x64 k-tile (elems)
#define SZ_WA (12*TSZ*2)           // 110592  (12 k-tiles for CH_A=768)
#define SZ_WC (6*TSZ*2)            // 55296   (6 k-tiles for CH_C=384)
#define SZ_AB (6*TSZ*2)            // 55296   (A buffer: 384-wide)
#define REC_SMEM (SZ_WA+SZ_WC+SZ_AB)   // 221184
#define BIG_SMEM (3*(128+64)*LDT*2)    // 82944

// ---------------- device globals (no allocations allowed) -------------------
__device__ __nv_bfloat16 g_xp [(size_t)MROWS*KP];   // x tri-split (hi,lo,hi)
__device__ __nv_bfloat16 g_hsp[(size_t)MROWS*KP];   // hs tri-split
__device__ __nv_bfloat16 g_wp [7*WPSZ];             // weights tri-split (hi,hi,lo)
__device__ float g_xz[(size_t)SEQ*BHD];             // xz preact, += rec z-sum
__device__ float g_xr[(size_t)SEQ*BHD];             // xr preact, += rec r-sum
__device__ float g_xn[(size_t)SEQ*BHD];             // xn preact, += rec n-sum
__device__ float g_h [BHD];
__device__ __nv_bfloat16 g_hp [BAT*KP];             // h tri-split
__device__ __nv_bfloat16 g_rhp[BAT*KP];             // r*h tri-split
__device__ unsigned g_flags[GRID_REC * 32];         // barrier flags, 128B spaced

// ---------------- helpers ----------------------------------------------------
__device__ __forceinline__ void trisplit(float v, __nv_bfloat16& hi, __nv_bfloat16& lo) {
    hi = __float2bfloat16(v);
    lo = __float2bfloat16(v - __bfloat162float(hi));
}

__device__ __forceinline__ uint32_t smem_u32(const void* p) {
    return (uint32_t)__cvta_generic_to_shared(p);
}

__device__ __forceinline__ void ldsm_x4(uint32_t* r, uint32_t addr) {
    asm volatile("ldmatrix.sync.aligned.m8n8.x4.shared.b16 {%0,%1,%2,%3}, [%4];"
                 : "=r"(r[0]), "=r"(r[1]), "=r"(r[2]), "=r"(r[3]) : "r"(addr));
}

__device__ __forceinline__ void mma_bf16(float* d, const uint32_t* a,
                                         uint32_t b0, uint32_t b1) {
    asm volatile("mma.sync.aligned.m16n8k16.row.col.f32.bf16.bf16.f32 "
                 "{%0,%1,%2,%3},{%4,%5,%6,%7},{%8,%9},{%0,%1,%2,%3};"
                 : "+f"(d[0]), "+f"(d[1]), "+f"(d[2]), "+f"(d[3])
                 : "r"(a[0]), "r"(a[1]), "r"(a[2]), "r"(a[3]), "r"(b0), "r"(b1));
}

__device__ __forceinline__ void cp_async16(uint32_t saddr, const void* gptr) {
    asm volatile("cp.async.cg.shared.global [%0], [%1], 16;" :: "r"(saddr), "l"(gptr));
}
__device__ __forceinline__ void cp_commit() {
    asm volatile("cp.async.commit_group;");
}
template <int N>
__device__ __forceinline__ void cp_wait() {
    asm volatile("cp.async.wait_group %0;" :: "n"(N));
}

// ---------------- conversion kernels ----------------------------------------
__global__ void conv_a_kernel(const float* __restrict__ x) {
    size_t i = (size_t)blockIdx.x * 256 + threadIdx.x;
    float v = x[i];
    size_t m = i >> 10, k = i & 1023;
    __nv_bfloat16 hi, lo; trisplit(v, hi, lo);
    __nv_bfloat16* dst = g_xp + m * KP;
    dst[k] = hi; dst[1024 + k] = lo; dst[2048 + k] = hi;
}

__global__ void conv_w_kernel(const float* w0, const float* w1, const float* w2,
                              const float* w3, const float* w4, const float* w5,
                              const float* w6) {
    int z = blockIdx.z;
    const float* src = (z==0)?w0:(z==1)?w1:(z==2)?w2:(z==3)?w3:(z==4)?w4:(z==5)?w5:w6;
    size_t i = (size_t)blockIdx.x * 256 + threadIdx.x;
    float v = src[i];
    size_t row = i >> 10, k = i & 1023;
    __nv_bfloat16 hi, lo; trisplit(v, hi, lo);
    __nv_bfloat16* dst = g_wp + (size_t)z * WPSZ + row * KP;
    dst[k] = hi; dst[1024 + k] = hi; dst[2048 + k] = lo;
}

__global__ void init_h_kernel(const float* __restrict__ h0) {
    int i = blockIdx.x * 256 + threadIdx.x;
    float v = h0[i];
    g_h[i] = v;
    int b = i >> 10, k = i & 1023;
    __nv_bfloat16 hi, lo; trisplit(v, hi, lo);
    __nv_bfloat16* dst = g_hp + (size_t)b * KP;
    dst[k] = hi; dst[1024 + k] = lo; dst[2048 + k] = hi;
    if (i < GRID_REC * 32) g_flags[i] = 0;        // reset barrier flags per launch
}

// ---------------- grid barrier: flag array, contention-free -----------------
__device__ __forceinline__ void gbar(unsigned& phase) {
    phase++;
    __syncthreads();
    if (threadIdx.x == 0) {
        asm volatile("st.release.gpu.u32 [%0], %1;"
                     :: "l"(&g_flags[blockIdx.x * 32]), "r"(phase) : "memory");
    }
    if (threadIdx.x < GRID_REC) {
        unsigned v;
        do {
            asm volatile("ld.acquire.gpu.u32 %0, [%1];"
                         : "=r"(v) : "l"(&g_flags[threadIdx.x * 32]) : "memory");
        } while (v < phase);
    }
    __syncthreads();
}

// ---------------- big bf16 GEMM, 3-stage cp.async pipeline (known-good) -----
__global__ __launch_bounds__(256)
void gemm_bf16p(int a_sel, int w_base, int c_mode,
                const float* __restrict__ bias0, const float* __restrict__ bias1,
                const float* __restrict__ bias2, float* __restrict__ Cext) {
    const int z = blockIdx.z;
    const __nv_bfloat16* A = a_sel ? g_hsp : g_xp;
    const __nv_bfloat16* W = g_wp + (size_t)(w_base + z) * WPSZ;
    const float* bias = (z == 0) ? bias0 : (z == 1) ? bias1 : bias2;
    float* C = (c_mode == 1) ? Cext : (z == 0 ? g_xz : z == 1 ? g_xr : g_xn);

    extern __shared__ char dynsm[];
    __nv_bfloat16 (*sA)[128 * LDT] = (__nv_bfloat16 (*)[128 * LDT])dynsm;
    __nv_bfloat16 (*sB)[64 * LDT]  =
        (__nv_bfloat16 (*)[64 * LDT])(dynsm + 3 * 128 * LDT * 2);

    const int m0 = blockIdx.y * 128, n0 = blockIdx.x * 64;
    const int t = threadIdx.x, lane = t & 31, w8 = t >> 5;
    const int wm = w8 >> 1, wn = w8 & 1;

    auto load_stage = [&](int st, int kt) {
        const int kb = kt * 64;
        #pragma unroll
        for (int q = 0; q < 4; ++q) {
            int c = t + q * 256;
            int r = c >> 3, off = (c & 7) * 8;
            cp_async16(smem_u32(&sA[st][r * LDT + off]),
                       A + (size_t)(m0 + r) * KP + kb + off);
        }
        #pragma unroll
        for (int q = 0; q < 2; ++q) {
            int c = t + q * 256;
            int r = c >> 3, off = (c & 7) * 8;
            cp_async16(smem_u32(&sB[st][r * LDT + off]),
                       W + (size_t)(n0 + r) * KP + kb + off);
        }
        cp_commit();
    };

    float acc[2][4][4] = {};
    load_stage(0, 0);
    load_stage(1, 1);

    const int NIT = KP / 64;                       // 48
    for (int kt = 0; kt < NIT; ++kt) {
        cp_wait<1>();
        __syncthreads();
        const int st = kt % 3;
        #pragma unroll
        for (int kk = 0; kk < 4; ++kk) {
            const int ks = kk * 16;
            uint32_t aF[2][4], bF[2][4];
            #pragma unroll
            for (int mi = 0; mi < 2; ++mi) {
                int arow = wm * 32 + mi * 16 + (lane & 15);
                int acol = ks + ((lane >> 4) << 3);
                ldsm_x4(aF[mi], smem_u32(&sA[st][arow * LDT + acol]));
            }
            #pragma unroll
            for (int nq = 0; nq < 2; ++nq) {
                int brow = wn * 32 + nq * 16 + (lane & 7) + (((lane >> 4) & 1) << 3);
                int bcol = ks + (((lane >> 3) & 1) << 3);
                ldsm_x4(bF[nq], smem_u32(&sB[st][brow * LDT + bcol]));
            }
            #pragma unroll
            for (int mi = 0; mi < 2; ++mi)
                #pragma unroll
                for (int nq = 0; nq < 2; ++nq) {
                    mma_bf16(acc[mi][2 * nq],     aF[mi], bF[nq][0], bF[nq][1]);
                    mma_bf16(acc[mi][2 * nq + 1], aF[mi], bF[nq][2], bF[nq][3]);
                }
        }
        if (kt + 2 < NIT) load_stage((kt + 2) % 3, kt + 2);
        else cp_commit();
    }

    #pragma unroll
    for (int mi = 0; mi < 2; ++mi)
        #pragma unroll
        for (int ni = 0; ni < 4; ++ni) {
            int row = m0 + wm * 32 + mi * 16 + (lane >> 2);
            int col = n0 + wn * 32 + ni * 8 + (lane & 3) * 2;
            float b0 = bias[col], b1 = bias[col + 1];
            float* a = acc[mi][ni];
            *(float2*)&C[(size_t)row * DH + col]       = make_float2(a[0] + b0, a[1] + b1);
            *(float2*)&C[(size_t)(row + 8) * DH + col] = make_float2(a[2] + b0, a[3] + b1);
        }
}

// ---------------- recurrence MMA: 64x64 output tile, resident operands ------
// 8 warps (2m x 4n), warp tile 32x16. acc[2][2][4].
template <int NT>
__device__ __forceinline__ void mma64(
    const __nv_bfloat16* sAb,     // [NT][64*LDT]
    const __nv_bfloat16* sW,      // [NT][64*LDT]
    float acc[2][2][4]) {
    const int t = threadIdx.x, lane = t & 31, w8 = t >> 5;
    const int wm = w8 >> 2, wn = w8 & 3;

    #pragma unroll
    for (int kt = 0; kt < NT; ++kt) {
        const __nv_bfloat16* At = sAb + kt * TSZ;
        const __nv_bfloat16* Wt = sW  + kt * TSZ;
        #pragma unroll
        for (int kk = 0; kk < 4; ++kk) {
            const int ks = kk * 16;
            uint32_t aF[2][4], bF[4];
            #pragma unroll
            for (int mi = 0; mi < 2; ++mi) {
                int arow = wm * 32 + mi * 16 + (lane & 15);
                int acol = ks + ((lane >> 4) << 3);
                ldsm_x4(aF[mi], smem_u32(At + arow * LDT + acol));
            }
            int brow = wn * 16 + (lane & 7) + (((lane >> 4) & 1) << 3);
            int bcol = ks + (((lane >> 3) & 1) << 3);
            ldsm_x4(bF, smem_u32(Wt + brow * LDT + bcol));
            #pragma unroll
            for (int mi = 0; mi < 2; ++mi) {
                mma_bf16(acc[mi][0], aF[mi], bF[0], bF[1]);
                mma_bf16(acc[mi][1], aF[mi], bF[2], bF[3]);
            }
        }
    }
}

// atomic-accumulate the 64x64 tile into dst (pre-initialized with x-projection)
__device__ __forceinline__ void red64(
    float* __restrict__ dst, int n0, const float acc[2][2][4]) {
    const int lane = threadIdx.x & 31, w8 = threadIdx.x >> 5;
    const int wm = w8 >> 2, wn = w8 & 3;
    #pragma unroll
    for (int mi = 0; mi < 2; ++mi)
        #pragma unroll
        for (int ni = 0; ni < 2; ++ni) {
            int row = wm * 32 + mi * 16 + (lane >> 2);
            int col = n0 + wn * 16 + ni * 8 + (lane & 3) * 2;
            const float* a = acc[mi][ni];
            atomicAdd(&dst[(size_t)row * DH + col],           a[0]);
            atomicAdd(&dst[(size_t)row * DH + col + 1],       a[1]);
            atomicAdd(&dst[(size_t)(row + 8) * DH + col],     a[2]);
            atomicAdd(&dst[(size_t)(row + 8) * DH + col + 1], a[3]);
        }
}

// ---------------- persistent recurrence -------------------------------------
// smem: sWA[12][64*LDT] | sWC[6][64*LDT] | sAb[6][64*LDT]
__global__ __launch_bounds__(REC_THREADS)
void recurrence_kernel() {
    extern __shared__ char dynbuf[];
    __nv_bfloat16* sWA = (__nv_bfloat16*)dynbuf;
    __nv_bfloat16* sWC = (__nv_bfloat16*)(dynbuf + SZ_WA);
    __nv_bfloat16* sAb = (__nv_bfloat16*)(dynbuf + SZ_WA + SZ_WC);

    const int bid = blockIdx.x;
    const int t = threadIdx.x;
    unsigned phase = 0;

    // phase A: gate(2) x ntile(16 of 64 cols) x ks(4 of 768)
    const int gateA = bid >> 6;
    const int subA  = bid & 63;
    const int n0A   = (subA >> 2) * 64;
    const int k0A   = (subA & 3) * CH_A;
    const __nv_bfloat16* WA = g_wp + (size_t)(3 + gateA) * WPSZ + (size_t)n0A * KP;

    // phase C: ntile(16 of 64 cols) x ks(8 of 384)
    const int n0C = (bid >> 3) * 64;
    const int k0C = (bid & 7) * CH_C;
    const __nv_bfloat16* WC = g_wp + (size_t)5 * WPSZ + (size_t)n0C * KP;

    // ---- one-time: preload all W chunks into resident smem ----
    // WA: 12 tiles x 64 rows x 8 chunks = 6144 chunks (24/thread)
    #pragma unroll
    for (int q = 0; q < 24; ++q) {
        int c = t + q * 256;
        int kt = c >> 9, r = (c >> 3) & 63, off = (c & 7) * 8;
        cp_async16(smem_u32(sWA + kt * TSZ + r * LDT + off),
                   WA + (size_t)r * KP + k0A + kt * 64 + off);
    }
    // WC: 6 tiles x 512 = 3072 chunks (12/thread)
    #pragma unroll
    for (int q = 0; q < 12; ++q) {
        int c = t + q * 256;
        int kt = c >> 9, r = (c >> 3) & 63, off = (c & 7) * 8;
        cp_async16(smem_u32(sWC + kt * TSZ + r * LDT + off),
                   WC + (size_t)r * KP + k0C + kt * 64 + off);
    }
    cp_commit();
    cp_wait<0>();
    __syncthreads();

    for (int s = 0; s < SEQ; ++s) {
        // ============ phase A: z|r GEMM (full 768 chunk in 2 halves) =======
        {
            float acc[2][2][4] = {};
            #pragma unroll
            for (int h = 0; h < 2; ++h) {
                // load A = g_hp[:, k0A+h*384 : +384] -> sAb (3072 chunks)
                #pragma unroll
                for (int q = 0; q < 12; ++q) {
                    int c = t + q * 256;
                    int kt = c >> 9, r = (c >> 3) & 63, off = (c & 7) * 8;
                    cp_async16(smem_u32(sAb + kt * TSZ + r * LDT + off),
                               g_hp + (size_t)r * KP + k0A + h * 384 + kt * 64 + off);
                }
                cp_commit();
                cp_wait<0>();
                __syncthreads();
                mma64<6>(sAb, sWA + h * (6 * TSZ), acc);
                if (h == 0) __syncthreads();   // drain readers before refill
            }
            float* dst = (gateA == 0 ? g_xz : g_xr) + (size_t)s * BHD;
            red64(dst, n0A, acc);
        }
        gbar(phase);

        // ============ phase B: sigmoid(r-preact) * h -> rh tri-split =======
        {
            const float* xr = g_xr + (size_t)s * BHD;
            #pragma unroll
            for (int q = 0; q < 2; ++q) {
                int i = bid * 512 + q * 256 + t;
                float r = 1.f / (1.f + __expf(-xr[i]));
                float rh = r * g_h[i];
                int b = i >> 10, k = i & 1023;
                __nv_bfloat16 hi, lo; trisplit(rh, hi, lo);
                __nv_bfloat16* dst = g_rhp + (size_t)b * KP;
                dst[k] = hi; dst[1024 + k] = lo; dst[2048 + k] = hi;
            }
        }
        gbar(phase);

        // ============ phase C: n GEMM (384 chunk) ============
        {
            #pragma unroll
            for (int q = 0; q < 12; ++q) {
                int c = t + q * 256;
                int kt = c >> 9, r = (c >> 3) & 63, off = (c & 7) * 8;
                cp_async16(smem_u32(sAb + kt * TSZ + r * LDT + off),
                           g_rhp + (size_t)r * KP + k0C + kt * 64 + off);
            }
            cp_commit();
            cp_wait<0>();
            __syncthreads();

            float acc[2][2][4] = {};
            mma64<6>(sAb, sWC, acc);
            red64(g_xn + (size_t)s * BHD, n0C, acc);
        }
        gbar(phase);

        // ============ phase D: z,n activations + h update ============
        {
            const float* xz = g_xz + (size_t)s * BHD;
            const float* xn = g_xn + (size_t)s * BHD;
            #pragma unroll
            for (int q = 0; q < 2; ++q) {
                int i = bid * 512 + q * 256 + t;
                float zv = 1.f / (1.f + __expf(-xz[i]));
                float nv = tanhf(xn[i]);
                float h  = g_h[i];
                float hn = fmaf(zv, nv - h, h);
                g_h[i] = hn;
                int b = i >> 10, k = i & 1023;
                __nv_bfloat16 hi, lo; trisplit(hn, hi, lo);
                __nv_bfloat16* dh = g_hp + (size_t)b * KP;
                dh[k] = hi; dh[1024 + k] = lo; dh[2048 + k] = hi;
                __nv_bfloat16* ds = g_hsp + ((size_t)s * BAT + b) * KP;
                ds[k] = hi; ds[1024 + k] = lo; ds[2048 + k] = hi;
            }
        }
        gbar(phase);
    }
}

__global__ void copy_hlast_kernel(float* __restrict__ dst) {
    int i = blockIdx.x * 256 + threadIdx.x;
    dst[i] = g_h[i];
}

// ---------------- launch ----------------------------------------------------
extern "C" void kernel_launch(void* const* d_in, const int* in_sizes, int n_in,
                              void* d_out, int out_size) {
    const float* x   = (const float*)d_in[0];
    const float* h0  = (const float*)d_in[1];
    const float* Wxz = (const float*)d_in[2];
    const float* bxz = (const float*)d_in[3];
    const float* Whz = (const float*)d_in[4];
    const float* Wxr = (const float*)d_in[5];
    const float* bxr = (const float*)d_in[6];
    const float* Whr = (const float*)d_in[7];
    const float* Wxn = (const float*)d_in[8];
    const float* bxn = (const float*)d_in[9];
    const float* Whn = (const float*)d_in[10];
    const float* Why = (const float*)d_in[11];
    const float* bhy = (const float*)d_in[12];
    float* out = (float*)d_out;

    cudaFuncSetAttribute(recurrence_kernel,
                         cudaFuncAttributeMaxDynamicSharedMemorySize, REC_SMEM);
    cudaFuncSetAttribute(gemm_bf16p,
                         cudaFuncAttributeMaxDynamicSharedMemorySize, BIG_SMEM);

    conv_w_kernel<<<dim3(DH * DH / 256, 1, 7), 256>>>(Wxz, Wxr, Wxn, Whz, Whr, Whn, Why);
    conv_a_kernel<<<(size_t)MROWS * DH / 256, 256>>>(x);
    init_h_kernel<<<BHD / 256, 256>>>(h0);

    gemm_bf16p<<<dim3(DH / 64, MROWS / 128, 3), 256, BIG_SMEM>>>(
        0, 0, 0, bxz, bxr, bxn, nullptr);

    recurrence_kernel<<<GRID_REC, REC_THREADS, REC_SMEM>>>();

    gemm_bf16p<<<dim3(DH / 64, MROWS / 128, 1), 256, BIG_SMEM>>>(
        1, 6, 1, bhy, bhy, bhy, out);

    copy_hlast_kernel<<<BHD / 256, 256>>>(out + (size_t)MROWS * DH);
}

// round 16
// speedup vs baseline: 1.0633x; 1.0633x over previous
#include <cuda_runtime.h>
#include <cuda_bf16.h>
#include <cstdint>

#define SEQ   512
#define BAT   64
#define DH    1024
#define KP    3072                 // tri-split K' = 3*1024
#define MROWS (SEQ*BAT)            // 32768
#define BHD   (BAT*DH)             // 65536

#define GRID_REC 128
#define REC_THREADS 256
#define CH_ZR 384                  // phase-A k-chunk (8 splits)
#define CH_N  192                  // phase-C k-chunk (16 splits)
#define NIT_A (CH_ZR/64)           // 6
#define NIT_C (CH_N/64)            // 3
#define WPSZ  ((size_t)DH*KP)
#define LDT   72                   // smem row stride (bf16)
#define SZ_WA (NIT_A*128*LDT*2)    // 110592
#define SZ_WC (NIT_C*128*LDT*2)    // 55296
#define SZ_AB (NIT_A*64*LDT*2)     // 55296
#define REC_SMEM (SZ_WA+SZ_WC+SZ_AB)   // 221184
#define BIG_SMEM (3*(128+128)*LDT*2)   // 110592

// ---------------- device globals (no allocations allowed) -------------------
__device__ __nv_bfloat16 g_xp [(size_t)MROWS*KP];   // x tri-split (hi,lo,hi)
__device__ __nv_bfloat16 g_hsp[(size_t)MROWS*KP];   // hs tri-split
__device__ __nv_bfloat16 g_wp [7*WPSZ];             // weights tri-split (hi,hi,lo)
__device__ float g_xz[(size_t)SEQ*BHD];             // xz preact, += rec z-sum
__device__ float g_xr[(size_t)SEQ*BHD];             // xr preact, += rec r-sum
__device__ float g_xn[(size_t)SEQ*BHD];             // xn preact, += rec n-sum
__device__ float g_h [BHD];
__device__ __nv_bfloat16 g_hp [BAT*KP];             // h tri-split
__device__ __nv_bfloat16 g_rhp[BAT*KP];             // r*h tri-split
__device__ unsigned g_flags[GRID_REC * 32];         // barrier flags, 128B spaced

// ---------------- helpers ----------------------------------------------------
__device__ __forceinline__ void trisplit(float v, __nv_bfloat16& hi, __nv_bfloat16& lo) {
    hi = __float2bfloat16(v);
    lo = __float2bfloat16(v - __bfloat162float(hi));
}

__device__ __forceinline__ uint32_t smem_u32(const void* p) {
    return (uint32_t)__cvta_generic_to_shared(p);
}

__device__ __forceinline__ void ldsm_x4(uint32_t* r, uint32_t addr) {
    asm volatile("ldmatrix.sync.aligned.m8n8.x4.shared.b16 {%0,%1,%2,%3}, [%4];"
                 : "=r"(r[0]), "=r"(r[1]), "=r"(r[2]), "=r"(r[3]) : "r"(addr));
}

__device__ __forceinline__ void mma_bf16(float* d, const uint32_t* a,
                                         uint32_t b0, uint32_t b1) {
    asm volatile("mma.sync.aligned.m16n8k16.row.col.f32.bf16.bf16.f32 "
                 "{%0,%1,%2,%3},{%4,%5,%6,%7},{%8,%9},{%0,%1,%2,%3};"
                 : "+f"(d[0]), "+f"(d[1]), "+f"(d[2]), "+f"(d[3])
                 : "r"(a[0]), "r"(a[1]), "r"(a[2]), "r"(a[3]), "r"(b0), "r"(b1));
}

__device__ __forceinline__ void cp_async16(uint32_t saddr, const void* gptr) {
    asm volatile("cp.async.cg.shared.global [%0], [%1], 16;" :: "r"(saddr), "l"(gptr));
}
__device__ __forceinline__ void cp_commit() {
    asm volatile("cp.async.commit_group;");
}
template <int N>
__device__ __forceinline__ void cp_wait() {
    asm volatile("cp.async.wait_group %0;" :: "n"(N));
}

// ---------------- conversion kernels ----------------------------------------
__global__ void conv_a_kernel(const float* __restrict__ x) {
    size_t i = (size_t)blockIdx.x * 256 + threadIdx.x;
    float v = x[i];
    size_t m = i >> 10, k = i & 1023;
    __nv_bfloat16 hi, lo; trisplit(v, hi, lo);
    __nv_bfloat16* dst = g_xp + m * KP;
    dst[k] = hi; dst[1024 + k] = lo; dst[2048 + k] = hi;
}

__global__ void conv_w_kernel(const float* w0, const float* w1, const float* w2,
                              const float* w3, const float* w4, const float* w5,
                              const float* w6) {
    int z = blockIdx.z;
    const float* src = (z==0)?w0:(z==1)?w1:(z==2)?w2:(z==3)?w3:(z==4)?w4:(z==5)?w5:w6;
    size_t i = (size_t)blockIdx.x * 256 + threadIdx.x;
    float v = src[i];
    size_t row = i >> 10, k = i & 1023;
    __nv_bfloat16 hi, lo; trisplit(v, hi, lo);
    __nv_bfloat16* dst = g_wp + (size_t)z * WPSZ + row * KP;
    dst[k] = hi; dst[1024 + k] = hi; dst[2048 + k] = lo;
}

__global__ void init_h_kernel(const float* __restrict__ h0) {
    int i = blockIdx.x * 256 + threadIdx.x;
    float v = h0[i];
    g_h[i] = v;
    int b = i >> 10, k = i & 1023;
    __nv_bfloat16 hi, lo; trisplit(v, hi, lo);
    __nv_bfloat16* dst = g_hp + (size_t)b * KP;
    dst[k] = hi; dst[1024 + k] = lo; dst[2048 + k] = hi;
    if (i < GRID_REC * 32) g_flags[i] = 0;        // reset barrier flags per launch
}

// ---------------- grid barrier: flag array, contention-free -----------------
__device__ __forceinline__ void gbar(unsigned& phase) {
    phase++;
    __syncthreads();
    if (threadIdx.x == 0) {
        asm volatile("st.release.gpu.u32 [%0], %1;"
                     :: "l"(&g_flags[blockIdx.x * 32]), "r"(phase) : "memory");
    }
    if (threadIdx.x < GRID_REC) {
        unsigned v;
        do {
            asm volatile("ld.acquire.gpu.u32 %0, [%1];"
                         : "=r"(v) : "l"(&g_flags[threadIdx.x * 32]) : "memory");
        } while (v < phase);
    }
    __syncthreads();
}

// ---------------- big bf16 GEMM: BM=128, BN=128, 3-stage pipeline -----------
// 256 threads, 8 warps (4m x 2n), warp tile 32x64. acc[2][8][4] (64 floats).
__global__ __launch_bounds__(256)
void gemm_bf16p(int a_sel, int w_base, int c_mode,
                const float* __restrict__ bias0, const float* __restrict__ bias1,
                const float* __restrict__ bias2, float* __restrict__ Cext) {
    const int z = blockIdx.z;
    const __nv_bfloat16* A = a_sel ? g_hsp : g_xp;
    const __nv_bfloat16* W = g_wp + (size_t)(w_base + z) * WPSZ;
    const float* bias = (z == 0) ? bias0 : (z == 1) ? bias1 : bias2;
    float* C = (c_mode == 1) ? Cext : (z == 0 ? g_xz : z == 1 ? g_xr : g_xn);

    extern __shared__ char dynsm[];
    __nv_bfloat16 (*sA)[128 * LDT] = (__nv_bfloat16 (*)[128 * LDT])dynsm;
    __nv_bfloat16 (*sB)[128 * LDT] =
        (__nv_bfloat16 (*)[128 * LDT])(dynsm + 3 * 128 * LDT * 2);

    const int m0 = blockIdx.y * 128, n0 = blockIdx.x * 128;
    const int t = threadIdx.x, lane = t & 31, w8 = t >> 5;
    const int wm = w8 >> 1, wn = w8 & 1;

    auto load_stage = [&](int st, int kt) {
        const int kb = kt * 64;
        #pragma unroll
        for (int q = 0; q < 4; ++q) {              // A: 128x64 = 1024 chunks
            int c = t + q * 256;
            int r = c >> 3, off = (c & 7) * 8;
            cp_async16(smem_u32(&sA[st][r * LDT + off]),
                       A + (size_t)(m0 + r) * KP + kb + off);
        }
        #pragma unroll
        for (int q = 0; q < 4; ++q) {              // W: 128x64 = 1024 chunks
            int c = t + q * 256;
            int r = c >> 3, off = (c & 7) * 8;
            cp_async16(smem_u32(&sB[st][r * LDT + off]),
                       W + (size_t)(n0 + r) * KP + kb + off);
        }
        cp_commit();
    };

    float acc[2][8][4] = {};
    load_stage(0, 0);
    load_stage(1, 1);

    const int NIT = KP / 64;                       // 48
    for (int kt = 0; kt < NIT; ++kt) {
        cp_wait<1>();
        __syncthreads();
        const int st = kt % 3;
        #pragma unroll
        for (int kk = 0; kk < 4; ++kk) {
            const int ks = kk * 16;
            uint32_t aF[2][4], bF[4][4];
            #pragma unroll
            for (int mi = 0; mi < 2; ++mi) {
                int arow = wm * 32 + mi * 16 + (lane & 15);
                int acol = ks + ((lane >> 4) << 3);
                ldsm_x4(aF[mi], smem_u32(&sA[st][arow * LDT + acol]));
            }
            #pragma unroll
            for (int nq = 0; nq < 4; ++nq) {
                int brow = wn * 64 + nq * 16 + (lane & 7) + (((lane >> 4) & 1) << 3);
                int bcol = ks + (((lane >> 3) & 1) << 3);
                ldsm_x4(bF[nq], smem_u32(&sB[st][brow * LDT + bcol]));
            }
            #pragma unroll
            for (int mi = 0; mi < 2; ++mi)
                #pragma unroll
                for (int nq = 0; nq < 4; ++nq) {
                    mma_bf16(acc[mi][2 * nq],     aF[mi], bF[nq][0], bF[nq][1]);
                    mma_bf16(acc[mi][2 * nq + 1], aF[mi], bF[nq][2], bF[nq][3]);
                }
        }
        if (kt + 2 < NIT) load_stage((kt + 2) % 3, kt + 2);
        else cp_commit();
    }

    #pragma unroll
    for (int mi = 0; mi < 2; ++mi)
        #pragma unroll
        for (int ni = 0; ni < 8; ++ni) {
            int row = m0 + wm * 32 + mi * 16 + (lane >> 2);
            int col = n0 + wn * 64 + ni * 8 + (lane & 3) * 2;
            float b0 = bias[col], b1 = bias[col + 1];
            float* a = acc[mi][ni];
            *(float2*)&C[(size_t)row * DH + col]       = make_float2(a[0] + b0, a[1] + b1);
            *(float2*)&C[(size_t)(row + 8) * DH + col] = make_float2(a[2] + b0, a[3] + b1);
        }
}

// ---------------- recurrence MMA with fully-resident smem operands ----------
// (exact round-13 configuration: 64x128 tile, 8 warps 2m x 4n, 32x32 warp tile)
template <int NIT>
__device__ __forceinline__ void mma_resident(
    const __nv_bfloat16* sAb,     // [NIT][64*LDT]
    const __nv_bfloat16* sW,      // [NIT][128*LDT]
    float acc[2][4][4]) {
    const int t = threadIdx.x, lane = t & 31, w8 = t >> 5;
    const int wm = w8 >> 2, wn = w8 & 3;

    #pragma unroll
    for (int kt = 0; kt < NIT; ++kt) {
        const __nv_bfloat16* At = sAb + kt * (64 * LDT);
        const __nv_bfloat16* Wt = sW  + kt * (128 * LDT);
        #pragma unroll
        for (int kk = 0; kk < 4; ++kk) {
            const int ks = kk * 16;
            uint32_t aF[2][4], bF[2][4];
            #pragma unroll
            for (int mi = 0; mi < 2; ++mi) {
                int arow = wm * 32 + mi * 16 + (lane & 15);
                int acol = ks + ((lane >> 4) << 3);
                ldsm_x4(aF[mi], smem_u32(At + arow * LDT + acol));
            }
            #pragma unroll
            for (int nq = 0; nq < 2; ++nq) {
                int brow = wn * 32 + nq * 16 + (lane & 7) + (((lane >> 4) & 1) << 3);
                int bcol = ks + (((lane >> 3) & 1) << 3);
                ldsm_x4(bF[nq], smem_u32(Wt + brow * LDT + bcol));
            }
            #pragma unroll
            for (int mi = 0; mi < 2; ++mi)
                #pragma unroll
                for (int nq = 0; nq < 2; ++nq) {
                    mma_bf16(acc[mi][2 * nq],     aF[mi], bF[nq][0], bF[nq][1]);
                    mma_bf16(acc[mi][2 * nq + 1], aF[mi], bF[nq][2], bF[nq][3]);
                }
        }
    }
}

// RED-accumulate the 64x128 tile into dst (pre-initialized with x-projection)
__device__ __forceinline__ void red_tile(
    float* __restrict__ dst, int n0, const float acc[2][4][4]) {
    const int lane = threadIdx.x & 31, w8 = threadIdx.x >> 5;
    const int wm = w8 >> 2, wn = w8 & 3;
    #pragma unroll
    for (int mi = 0; mi < 2; ++mi)
        #pragma unroll
        for (int ni = 0; ni < 4; ++ni) {
            int row = wm * 32 + mi * 16 + (lane >> 2);
            int col = n0 + wn * 32 + ni * 8 + (lane & 3) * 2;
            const float* a = acc[mi][ni];
            atomicAdd(&dst[(size_t)row * DH + col],           a[0]);
            atomicAdd(&dst[(size_t)row * DH + col + 1],       a[1]);
            atomicAdd(&dst[(size_t)(row + 8) * DH + col],     a[2]);
            atomicAdd(&dst[(size_t)(row + 8) * DH + col + 1], a[3]);
        }
}

// ---------------- persistent recurrence (exact round-13) --------------------
__global__ __launch_bounds__(REC_THREADS)
void recurrence_kernel() {
    extern __shared__ char dynbuf[];
    __nv_bfloat16* sWA = (__nv_bfloat16*)dynbuf;
    __nv_bfloat16* sWC = (__nv_bfloat16*)(dynbuf + SZ_WA);
    __nv_bfloat16* sAb = (__nv_bfloat16*)(dynbuf + SZ_WA + SZ_WC);

    const int bid = blockIdx.x;
    const int t = threadIdx.x;
    unsigned phase = 0;

    // phase A: gate(2) x ntile(8 of 128 cols) x ks(8 of 384)
    const int gateA = bid >> 6;
    const int subA  = bid & 63;
    const int n0A   = (subA >> 3) * 128;
    const int k0A   = (subA & 7) * CH_ZR;
    const __nv_bfloat16* WA = g_wp + (size_t)(3 + gateA) * WPSZ + (size_t)n0A * KP;

    // phase C: ntile(8 of 128 cols) x ks(16 of 192)
    const int n0C = (bid >> 4) * 128;
    const int k0C = (bid & 15) * CH_N;
    const __nv_bfloat16* WC = g_wp + (size_t)5 * WPSZ + (size_t)n0C * KP;

    // ---- one-time: preload all W chunks into resident smem ----
    #pragma unroll
    for (int q = 0; q < 24; ++q) {
        int c = t + q * 256;
        int kt = c >> 10, r = (c >> 3) & 127, off = (c & 7) * 8;
        cp_async16(smem_u32(sWA + kt * (128 * LDT) + r * LDT + off),
                   WA + (size_t)r * KP + k0A + kt * 64 + off);
    }
    #pragma unroll
    for (int q = 0; q < 12; ++q) {
        int c = t + q * 256;
        int kt = c >> 10, r = (c >> 3) & 127, off = (c & 7) * 8;
        cp_async16(smem_u32(sWC + kt * (128 * LDT) + r * LDT + off),
                   WC + (size_t)r * KP + k0C + kt * 64 + off);
    }
    cp_commit();
    cp_wait<0>();
    __syncthreads();

    for (int s = 0; s < SEQ; ++s) {
        // ============ phase A: z|r GEMM, RED into g_xz|g_xr[s] ============
        {
            #pragma unroll
            for (int q = 0; q < 12; ++q) {
                int c = t + q * 256;
                int kt = c >> 9, r = (c >> 3) & 63, off = (c & 7) * 8;
                cp_async16(smem_u32(sAb + kt * (64 * LDT) + r * LDT + off),
                           g_hp + (size_t)r * KP + k0A + kt * 64 + off);
            }
            cp_commit();
            cp_wait<0>();
            __syncthreads();

            float acc[2][4][4] = {};
            mma_resident<NIT_A>(sAb, sWA, acc);
            float* dst = (gateA == 0 ? g_xz : g_xr) + (size_t)s * BHD;
            red_tile(dst, n0A, acc);
        }
        gbar(phase);

        // ============ phase B: sigmoid(r-preact) * h -> rh tri-split =======
        {
            const float* xr = g_xr + (size_t)s * BHD;
            #pragma unroll
            for (int q = 0; q < 2; ++q) {
                int i = bid * 512 + q * 256 + t;
                float r = 1.f / (1.f + __expf(-xr[i]));
                float rh = r * g_h[i];
                int b = i >> 10, k = i & 1023;
                __nv_bfloat16 hi, lo; trisplit(rh, hi, lo);
                __nv_bfloat16* dst = g_rhp + (size_t)b * KP;
                dst[k] = hi; dst[1024 + k] = lo; dst[2048 + k] = hi;
            }
        }
        gbar(phase);

        // ============ phase C: n GEMM, RED into g_xn[s] ============
        {
            #pragma unroll
            for (int q = 0; q < 6; ++q) {
                int c = t + q * 256;
                int kt = c >> 9, r = (c >> 3) & 63, off = (c & 7) * 8;
                cp_async16(smem_u32(sAb + kt * (64 * LDT) + r * LDT + off),
                           g_rhp + (size_t)r * KP + k0C + kt * 64 + off);
            }
            cp_commit();
            cp_wait<0>();
            __syncthreads();

            float acc[2][4][4] = {};
            mma_resident<NIT_C>(sAb, sWC, acc);
            red_tile(g_xn + (size_t)s * BHD, n0C, acc);
        }
        gbar(phase);

        // ============ phase D: z,n activations + h update ============
        {
            const float* xz = g_xz + (size_t)s * BHD;
            const float* xn = g_xn + (size_t)s * BHD;
            #pragma unroll
            for (int q = 0; q < 2; ++q) {
                int i = bid * 512 + q * 256 + t;
                float zv = 1.f / (1.f + __expf(-xz[i]));
                float nv = tanhf(xn[i]);
                float h  = g_h[i];
                float hn = fmaf(zv, nv - h, h);
                g_h[i] = hn;
                int b = i >> 10, k = i & 1023;
                __nv_bfloat16 hi, lo; trisplit(hn, hi, lo);
                __nv_bfloat16* dh = g_hp + (size_t)b * KP;
                dh[k] = hi; dh[1024 + k] = lo; dh[2048 + k] = hi;
                __nv_bfloat16* ds = g_hsp + ((size_t)s * BAT + b) * KP;
                ds[k] = hi; ds[1024 + k] = lo; ds[2048 + k] = hi;
            }
        }
        gbar(phase);
    }
}

__global__ void copy_hlast_kernel(float* __restrict__ dst) {
    int i = blockIdx.x * 256 + threadIdx.x;
    dst[i] = g_h[i];
}

// ---------------- launch ----------------------------------------------------
extern "C" void kernel_launch(void* const* d_in, const int* in_sizes, int n_in,
                              void* d_out, int out_size) {
    const float* x   = (const float*)d_in[0];
    const float* h0  = (const float*)d_in[1];
    const float* Wxz = (const float*)d_in[2];
    const float* bxz = (const float*)d_in[3];
    const float* Whz = (const float*)d_in[4];
    const float* Wxr = (const float*)d_in[5];
    const float* bxr = (const float*)d_in[6];
    const float* Whr = (const float*)d_in[7];
    const float* Wxn = (const float*)d_in[8];
    const float* bxn = (const float*)d_in[9];
    const float* Whn = (const float*)d_in[10];
    const float* Why = (const float*)d_in[11];
    const float* bhy = (const float*)d_in[12];
    float* out = (float*)d_out;

    cudaFuncSetAttribute(recurrence_kernel,
                         cudaFuncAttributeMaxDynamicSharedMemorySize, REC_SMEM);
    cudaFuncSetAttribute(gemm_bf16p,
                         cudaFuncAttributeMaxDynamicSharedMemorySize, BIG_SMEM);

    conv_w_kernel<<<dim3(DH * DH / 256, 1, 7), 256>>>(Wxz, Wxr, Wxn, Whz, Whr, Whn, Why);
    conv_a_kernel<<<(size_t)MROWS * DH / 256, 256>>>(x);
    init_h_kernel<<<BHD / 256, 256>>>(h0);

    gemm_bf16p<<<dim3(DH / 128, MROWS / 128, 3), 256, BIG_SMEM>>>(
        0, 0, 0, bxz, bxr, bxn, nullptr);

    recurrence_kernel<<<GRID_REC, REC_THREADS, REC_SMEM>>>();

    gemm_bf16p<<<dim3(DH / 128, MROWS / 128, 1), 256, BIG_SMEM>>>(
        1, 6, 1, bhy, bhy, bhy, out);

    copy_hlast_kernel<<<BHD / 256, 256>>>(out + (size_t)MROWS * DH);
}

// round 17
// speedup vs baseline: 1.0854x; 1.0208x over previous
#include <cuda_runtime.h>
#include <cuda_bf16.h>
#include <cstdint>

#define SEQ   512
#define BAT   64
#define DH    1024
#define KP    3072                 // tri-split K' = 3*1024
#define MROWS (SEQ*BAT)            // 32768
#define BHD   (BAT*DH)             // 65536

#define GRID_REC 128
#define REC_THREADS 256
#define CH_ZR 384                  // phase-A k-chunk (8 splits)
#define CH_N  192                  // phase-C k-chunk (16 splits)
#define NIT_A (CH_ZR/64)           // 6
#define NIT_C (CH_N/64)            // 3
#define WPSZ  ((size_t)DH*KP)
#define LDT   72                   // smem row stride (bf16)
#define TS    (64*LDT)             // A k-tile elems
#define WTS   (128*LDT)            // W k-tile elems
#define SZ_WA (NIT_A*WTS*2)        // 110592
#define SZ_WC (NIT_C*WTS*2)        // 55296
#define SZ_AB (NIT_A*TS*2)         // 55296
#define REC_SMEM (SZ_WA+SZ_WC+SZ_AB)   // 221184
#define BIG_SMEM (3*(256+128)*LDT*2)   // 165888

// ---------------- device globals (no allocations allowed) -------------------
__device__ __nv_bfloat16 g_xp [(size_t)MROWS*KP];   // x tri-split (hi,lo,hi)
__device__ __nv_bfloat16 g_hsp[(size_t)MROWS*KP];   // hs tri-split
__device__ __nv_bfloat16 g_wp [7*WPSZ];             // weights tri-split (hi,hi,lo)
__device__ float g_xz[(size_t)SEQ*BHD];             // xz preact, += rec z-sum
__device__ float g_xr[(size_t)SEQ*BHD];             // xr preact, += rec r-sum
__device__ float g_xn[(size_t)SEQ*BHD];             // xn preact, += rec n-sum
__device__ float g_h [BHD];
__device__ __nv_bfloat16 g_hp [BAT*KP];             // h tri-split
__device__ __nv_bfloat16 g_rhp[BAT*KP];             // r*h tri-split
__device__ unsigned g_flags[GRID_REC * 32];         // barrier flags, 128B spaced

// ---------------- helpers ----------------------------------------------------
__device__ __forceinline__ void trisplit(float v, __nv_bfloat16& hi, __nv_bfloat16& lo) {
    hi = __float2bfloat16(v);
    lo = __float2bfloat16(v - __bfloat162float(hi));
}

__device__ __forceinline__ uint32_t smem_u32(const void* p) {
    return (uint32_t)__cvta_generic_to_shared(p);
}

__device__ __forceinline__ void ldsm_x4(uint32_t* r, uint32_t addr) {
    asm volatile("ldmatrix.sync.aligned.m8n8.x4.shared.b16 {%0,%1,%2,%3}, [%4];"
                 : "=r"(r[0]), "=r"(r[1]), "=r"(r[2]), "=r"(r[3]) : "r"(addr));
}

__device__ __forceinline__ void mma_bf16(float* d, const uint32_t* a,
                                         uint32_t b0, uint32_t b1) {
    asm volatile("mma.sync.aligned.m16n8k16.row.col.f32.bf16.bf16.f32 "
                 "{%0,%1,%2,%3},{%4,%5,%6,%7},{%8,%9},{%0,%1,%2,%3};"
                 : "+f"(d[0]), "+f"(d[1]), "+f"(d[2]), "+f"(d[3])
                 : "r"(a[0]), "r"(a[1]), "r"(a[2]), "r"(a[3]), "r"(b0), "r"(b1));
}

__device__ __forceinline__ void cp_async16(uint32_t saddr, const void* gptr) {
    asm volatile("cp.async.cg.shared.global [%0], [%1], 16;" :: "r"(saddr), "l"(gptr));
}
__device__ __forceinline__ void cp_commit() {
    asm volatile("cp.async.commit_group;");
}
template <int N>
__device__ __forceinline__ void cp_wait() {
    asm volatile("cp.async.wait_group %0;" :: "n"(N));
}

// ---------------- conversion kernels ----------------------------------------
__global__ void conv_a_kernel(const float* __restrict__ x) {
    size_t i = (size_t)blockIdx.x * 256 + threadIdx.x;
    float v = x[i];
    size_t m = i >> 10, k = i & 1023;
    __nv_bfloat16 hi, lo; trisplit(v, hi, lo);
    __nv_bfloat16* dst = g_xp + m * KP;
    dst[k] = hi; dst[1024 + k] = lo; dst[2048 + k] = hi;
}

__global__ void conv_w_kernel(const float* w0, const float* w1, const float* w2,
                              const float* w3, const float* w4, const float* w5,
                              const float* w6) {
    int z = blockIdx.z;
    const float* src = (z==0)?w0:(z==1)?w1:(z==2)?w2:(z==3)?w3:(z==4)?w4:(z==5)?w5:w6;
    size_t i = (size_t)blockIdx.x * 256 + threadIdx.x;
    float v = src[i];
    size_t row = i >> 10, k = i & 1023;
    __nv_bfloat16 hi, lo; trisplit(v, hi, lo);
    __nv_bfloat16* dst = g_wp + (size_t)z * WPSZ + row * KP;
    dst[k] = hi; dst[1024 + k] = hi; dst[2048 + k] = lo;
}

__global__ void init_h_kernel(const float* __restrict__ h0) {
    int i = blockIdx.x * 256 + threadIdx.x;
    float v = h0[i];
    g_h[i] = v;
    int b = i >> 10, k = i & 1023;
    __nv_bfloat16 hi, lo; trisplit(v, hi, lo);
    __nv_bfloat16* dst = g_hp + (size_t)b * KP;
    dst[k] = hi; dst[1024 + k] = lo; dst[2048 + k] = hi;
    if (i < GRID_REC * 32) g_flags[i] = 0;        // reset barrier flags per launch
}

// ---------------- grid barrier: flag array, contention-free -----------------
__device__ __forceinline__ void gbar(unsigned& phase) {
    phase++;
    __syncthreads();
    if (threadIdx.x == 0) {
        asm volatile("st.release.gpu.u32 [%0], %1;"
                     :: "l"(&g_flags[blockIdx.x * 32]), "r"(phase) : "memory");
    }
    if (threadIdx.x < GRID_REC) {
        unsigned v;
        do {
            asm volatile("ld.acquire.gpu.u32 %0, [%1];"
                         : "=r"(v) : "l"(&g_flags[threadIdx.x * 32]) : "memory");
        } while (v < phase);
    }
    __syncthreads();
}

// ---------------- big bf16 GEMM: BM=256, BN=128, 512 threads ----------------
// 16 warps (4m x 4n), warp tile 64x32. acc[4][4][4] (64 floats).
__global__ __launch_bounds__(512, 1)
void gemm_bf16p(int a_sel, int w_base, int c_mode,
                const float* __restrict__ bias0, const float* __restrict__ bias1,
                const float* __restrict__ bias2, float* __restrict__ Cext) {
    const int z = blockIdx.z;
    const __nv_bfloat16* A = a_sel ? g_hsp : g_xp;
    const __nv_bfloat16* W = g_wp + (size_t)(w_base + z) * WPSZ;
    const float* bias = (z == 0) ? bias0 : (z == 1) ? bias1 : bias2;
    float* C = (c_mode == 1) ? Cext : (z == 0 ? g_xz : z == 1 ? g_xr : g_xn);

    extern __shared__ char dynsm[];
    __nv_bfloat16 (*sA)[256 * LDT] = (__nv_bfloat16 (*)[256 * LDT])dynsm;
    __nv_bfloat16 (*sB)[128 * LDT] =
        (__nv_bfloat16 (*)[128 * LDT])(dynsm + 3 * 256 * LDT * 2);

    const int m0 = blockIdx.y * 256, n0 = blockIdx.x * 128;
    const int t = threadIdx.x, lane = t & 31, w16 = t >> 5;
    const int wm = w16 >> 2, wn = w16 & 3;

    auto load_stage = [&](int st, int kt) {
        const int kb = kt * 64;
        #pragma unroll
        for (int q = 0; q < 4; ++q) {              // A: 256x64 = 2048 chunks
            int c = t + q * 512;
            int r = c >> 3, off = (c & 7) * 8;
            cp_async16(smem_u32(&sA[st][r * LDT + off]),
                       A + (size_t)(m0 + r) * KP + kb + off);
        }
        #pragma unroll
        for (int q = 0; q < 2; ++q) {              // W: 128x64 = 1024 chunks
            int c = t + q * 512;
            int r = c >> 3, off = (c & 7) * 8;
            cp_async16(smem_u32(&sB[st][r * LDT + off]),
                       W + (size_t)(n0 + r) * KP + kb + off);
        }
        cp_commit();
    };

    float acc[4][4][4] = {};
    load_stage(0, 0);
    load_stage(1, 1);

    const int NIT = KP / 64;                       // 48
    for (int kt = 0; kt < NIT; ++kt) {
        cp_wait<1>();
        __syncthreads();
        const int st = kt % 3;
        #pragma unroll
        for (int kk = 0; kk < 4; ++kk) {
            const int ks = kk * 16;
            uint32_t aF[4][4], bF[2][4];
            #pragma unroll
            for (int mi = 0; mi < 4; ++mi) {
                int arow = wm * 64 + mi * 16 + (lane & 15);
                int acol = ks + ((lane >> 4) << 3);
                ldsm_x4(aF[mi], smem_u32(&sA[st][arow * LDT + acol]));
            }
            #pragma unroll
            for (int nq = 0; nq < 2; ++nq) {
                int brow = wn * 32 + nq * 16 + (lane & 7) + (((lane >> 4) & 1) << 3);
                int bcol = ks + (((lane >> 3) & 1) << 3);
                ldsm_x4(bF[nq], smem_u32(&sB[st][brow * LDT + bcol]));
            }
            #pragma unroll
            for (int mi = 0; mi < 4; ++mi)
                #pragma unroll
                for (int nq = 0; nq < 2; ++nq) {
                    mma_bf16(acc[mi][2 * nq],     aF[mi], bF[nq][0], bF[nq][1]);
                    mma_bf16(acc[mi][2 * nq + 1], aF[mi], bF[nq][2], bF[nq][3]);
                }
        }
        if (kt + 2 < NIT) load_stage((kt + 2) % 3, kt + 2);
        else cp_commit();
    }

    #pragma unroll
    for (int mi = 0; mi < 4; ++mi)
        #pragma unroll
        for (int ni = 0; ni < 4; ++ni) {
            int row = m0 + wm * 64 + mi * 16 + (lane >> 2);
            int col = n0 + wn * 32 + ni * 8 + (lane & 3) * 2;
            float b0 = bias[col], b1 = bias[col + 1];
            float* a = acc[mi][ni];
            *(float2*)&C[(size_t)row * DH + col]       = make_float2(a[0] + b0, a[1] + b1);
            *(float2*)&C[(size_t)(row + 8) * DH + col] = make_float2(a[2] + b0, a[3] + b1);
        }
}

// ---------------- recurrence MMA: one 64-wide k-tile against 128-row W ------
// 8 warps (2m x 4n), warp tile 32x32 -> 64x128 output tile.
__device__ __forceinline__ void mma_one(
    const __nv_bfloat16* At,      // [64][LDT]
    const __nv_bfloat16* Wt,      // [128][LDT]
    float acc[2][4][4]) {
    const int t = threadIdx.x, lane = t & 31, w8 = t >> 5;
    const int wm = w8 >> 2, wn = w8 & 3;
    #pragma unroll
    for (int kk = 0; kk < 4; ++kk) {
        const int ks = kk * 16;
        uint32_t aF[2][4], bF[2][4];
        #pragma unroll
        for (int mi = 0; mi < 2; ++mi) {
            int arow = wm * 32 + mi * 16 + (lane & 15);
            int acol = ks + ((lane >> 4) << 3);
            ldsm_x4(aF[mi], smem_u32(At + arow * LDT + acol));
        }
        #pragma unroll
        for (int nq = 0; nq < 2; ++nq) {
            int brow = wn * 32 + nq * 16 + (lane & 7) + (((lane >> 4) & 1) << 3);
            int bcol = ks + (((lane >> 3) & 1) << 3);
            ldsm_x4(bF[nq], smem_u32(Wt + brow * LDT + bcol));
        }
        #pragma unroll
        for (int mi = 0; mi < 2; ++mi)
            #pragma unroll
            for (int nq = 0; nq < 2; ++nq) {
                mma_bf16(acc[mi][2 * nq],     aF[mi], bF[nq][0], bF[nq][1]);
                mma_bf16(acc[mi][2 * nq + 1], aF[mi], bF[nq][2], bF[nq][3]);
            }
    }
}

// RED-accumulate the 64x128 tile into dst (pre-initialized with x-projection)
__device__ __forceinline__ void red_tile(
    float* __restrict__ dst, int n0, const float acc[2][4][4]) {
    const int lane = threadIdx.x & 31, w8 = threadIdx.x >> 5;
    const int wm = w8 >> 2, wn = w8 & 3;
    #pragma unroll
    for (int mi = 0; mi < 2; ++mi)
        #pragma unroll
        for (int ni = 0; ni < 4; ++ni) {
            int row = wm * 32 + mi * 16 + (lane >> 2);
            int col = n0 + wn * 32 + ni * 8 + (lane & 3) * 2;
            const float* a = acc[mi][ni];
            atomicAdd(&dst[(size_t)row * DH + col],           a[0]);
            atomicAdd(&dst[(size_t)row * DH + col + 1],       a[1]);
            atomicAdd(&dst[(size_t)(row + 8) * DH + col],     a[2]);
            atomicAdd(&dst[(size_t)(row + 8) * DH + col + 1], a[3]);
        }
}

// ---------------- persistent recurrence -------------------------------------
// smem: sWA[6][128*LDT] | sWC[3][128*LDT] | sAb[6][64*LDT]
__global__ __launch_bounds__(REC_THREADS)
void recurrence_kernel() {
    extern __shared__ char dynbuf[];
    __nv_bfloat16* sWA = (__nv_bfloat16*)dynbuf;
    __nv_bfloat16* sWC = (__nv_bfloat16*)(dynbuf + SZ_WA);
    __nv_bfloat16* sAb = (__nv_bfloat16*)(dynbuf + SZ_WA + SZ_WC);

    const int bid = blockIdx.x;
    const int t = threadIdx.x;
    unsigned phase = 0;

    // phase A: gate(2) x ntile(8 of 128 cols) x ks(8 of 384)
    const int gateA = bid >> 6;
    const int subA  = bid & 63;
    const int n0A   = (subA >> 3) * 128;
    const int k0A   = (subA & 7) * CH_ZR;
    const __nv_bfloat16* WA = g_wp + (size_t)(3 + gateA) * WPSZ + (size_t)n0A * KP;

    // phase C: ntile(8 of 128 cols) x ks(16 of 192)
    const int n0C = (bid >> 4) * 128;
    const int k0C = (bid & 15) * CH_N;
    const __nv_bfloat16* WC = g_wp + (size_t)5 * WPSZ + (size_t)n0C * KP;

    // per-tile A loader: one 64x64 tile = 512 chunks, 2/thread
    auto loadA_tile = [&](int kt, const __nv_bfloat16* src, int k0) {
        #pragma unroll
        for (int q = 0; q < 2; ++q) {
            int c = t + q * 256;
            int r = c >> 3, off = (c & 7) * 8;
            cp_async16(smem_u32(sAb + kt * TS + r * LDT + off),
                       src + (size_t)r * KP + k0 + kt * 64 + off);
        }
    };

    // ---- one-time: preload all W chunks into resident smem ----
    #pragma unroll
    for (int q = 0; q < 24; ++q) {
        int c = t + q * 256;
        int kt = c >> 10, r = (c >> 3) & 127, off = (c & 7) * 8;
        cp_async16(smem_u32(sWA + kt * WTS + r * LDT + off),
                   WA + (size_t)r * KP + k0A + kt * 64 + off);
    }
    #pragma unroll
    for (int q = 0; q < 12; ++q) {
        int c = t + q * 256;
        int kt = c >> 10, r = (c >> 3) & 127, off = (c & 7) * 8;
        cp_async16(smem_u32(sWC + kt * WTS + r * LDT + off),
                   WC + (size_t)r * KP + k0C + kt * 64 + off);
    }
    cp_commit();
    cp_wait<0>();
    __syncthreads();

    for (int s = 0; s < SEQ; ++s) {
        // ============ phase A: z|r GEMM, RED into g_xz|g_xr[s] ============
        {
            // staged loads: groups {t0}, {t1}, {t2..5}
            loadA_tile(0, g_hp, k0A); cp_commit();
            loadA_tile(1, g_hp, k0A); cp_commit();
            #pragma unroll
            for (int kt = 2; kt < NIT_A; ++kt) loadA_tile(kt, g_hp, k0A);
            cp_commit();

            float acc[2][4][4] = {};
            cp_wait<2>(); __syncthreads();
            mma_one(sAb, sWA, acc);
            cp_wait<1>(); __syncthreads();
            mma_one(sAb + TS, sWA + WTS, acc);
            cp_wait<0>(); __syncthreads();
            #pragma unroll
            for (int kt = 2; kt < NIT_A; ++kt)
                mma_one(sAb + kt * TS, sWA + kt * WTS, acc);

            float* dst = (gateA == 0 ? g_xz : g_xr) + (size_t)s * BHD;
            red_tile(dst, n0A, acc);
        }
        gbar(phase);

        // ============ phase B: sigmoid(r-preact) * h -> rh tri-split =======
        {
            const float* xr = g_xr + (size_t)s * BHD;
            #pragma unroll
            for (int q = 0; q < 2; ++q) {
                int i = bid * 512 + q * 256 + t;
                float r = 1.f / (1.f + __expf(-xr[i]));
                float rh = r * g_h[i];
                int b = i >> 10, k = i & 1023;
                __nv_bfloat16 hi, lo; trisplit(rh, hi, lo);
                __nv_bfloat16* dst = g_rhp + (size_t)b * KP;
                dst[k] = hi; dst[1024 + k] = lo; dst[2048 + k] = hi;
            }
        }
        gbar(phase);

        // ============ phase C: n GEMM, RED into g_xn[s] ============
        {
            loadA_tile(0, g_rhp, k0C); cp_commit();
            loadA_tile(1, g_rhp, k0C); cp_commit();
            loadA_tile(2, g_rhp, k0C); cp_commit();

            float acc[2][4][4] = {};
            cp_wait<2>(); __syncthreads();
            mma_one(sAb, sWC, acc);
            cp_wait<1>(); __syncthreads();
            mma_one(sAb + TS, sWC + WTS, acc);
            cp_wait<0>(); __syncthreads();
            mma_one(sAb + 2 * TS, sWC + 2 * WTS, acc);

            red_tile(g_xn + (size_t)s * BHD, n0C, acc);
        }
        gbar(phase);

        // ============ phase D: z,n activations + h update ============
        {
            const float* xz = g_xz + (size_t)s * BHD;
            const float* xn = g_xn + (size_t)s * BHD;
            #pragma unroll
            for (int q = 0; q < 2; ++q) {
                int i = bid * 512 + q * 256 + t;
                float zv = 1.f / (1.f + __expf(-xz[i]));
                float nv = tanhf(xn[i]);
                float h  = g_h[i];
                float hn = fmaf(zv, nv - h, h);
                g_h[i] = hn;
                int b = i >> 10, k = i & 1023;
                __nv_bfloat16 hi, lo; trisplit(hn, hi, lo);
                __nv_bfloat16* dh = g_hp + (size_t)b * KP;
                dh[k] = hi; dh[1024 + k] = lo; dh[2048 + k] = hi;
                __nv_bfloat16* ds = g_hsp + ((size_t)s * BAT + b) * KP;
                ds[k] = hi; ds[1024 + k] = lo; ds[2048 + k] = hi;
            }
        }
        gbar(phase);
    }
}

__global__ void copy_hlast_kernel(float* __restrict__ dst) {
    int i = blockIdx.x * 256 + threadIdx.x;
    dst[i] = g_h[i];
}

// ---------------- launch ----------------------------------------------------
extern "C" void kernel_launch(void* const* d_in, const int* in_sizes, int n_in,
                              void* d_out, int out_size) {
    const float* x   = (const float*)d_in[0];
    const float* h0  = (const float*)d_in[1];
    const float* Wxz = (const float*)d_in[2];
    const float* bxz = (const float*)d_in[3];
    const float* Whz = (const float*)d_in[4];
    const float* Wxr = (const float*)d_in[5];
    const float* bxr = (const float*)d_in[6];
    const float* Whr = (const float*)d_in[7];
    const float* Wxn = (const float*)d_in[8];
    const float* bxn = (const float*)d_in[9];
    const float* Whn = (const float*)d_in[10];
    const float* Why = (const float*)d_in[11];
    const float* bhy = (const float*)d_in[12];
    float* out = (float*)d_out;

    cudaFuncSetAttribute(recurrence_kernel,
                         cudaFuncAttributeMaxDynamicSharedMemorySize, REC_SMEM);
    cudaFuncSetAttribute(gemm_bf16p,
                         cudaFuncAttributeMaxDynamicSharedMemorySize, BIG_SMEM);

    conv_w_kernel<<<dim3(DH * DH / 256, 1, 7), 256>>>(Wxz, Wxr, Wxn, Whz, Whr, Whn, Why);
    conv_a_kernel<<<(size_t)MROWS * DH / 256, 256>>>(x);
    init_h_kernel<<<BHD / 256, 256>>>(h0);

    gemm_bf16p<<<dim3(DH / 128, MROWS / 256, 3), 512, BIG_SMEM>>>(
        0, 0, 0, bxz, bxr, bxn, nullptr);

    recurrence_kernel<<<GRID_REC, REC_THREADS, REC_SMEM>>>();

    gemm_bf16p<<<dim3(DH / 128, MROWS / 256, 1), 512, BIG_SMEM>>>(
        1, 6, 1, bhy, bhy, bhy, out);

    copy_hlast_kernel<<<BHD / 256, 256>>>(out + (size_t)MROWS * DH);
}